// round 1
// baseline (speedup 1.0000x reference)
#include <cuda_runtime.h>
#include <cuda_bf16.h>

// YOLOv3 decode: x [N=16, A*(5+C)=255, H=76, W=76] fp32 -> out [N, A*H*W, 85] fp32
// out[n, a, h*W+w, c] = f_c( x[n, a, c, h, w] )
//   c==0: (sigmoid(v)+w)/W    c==1: (sigmoid(v)+h)/H
//   c==2: exp(v)*aw/608       c==3: exp(v)*ah/608
//   c>=4: sigmoid(v)
// Pure HBM-bound transpose+elementwise. Tiled via smem: one block per (slice, h-row).
// Loads: 85 rows x 19 float4 coalesced. Stores: 76*85 = 6460 contiguous floats.

#define YW 76
#define YH 76
#define YHW 5776
#define YC 85
#define YA 3
#define YTPB 256
#define YSTRIDE 77   // odd smem row stride -> conflict-free transposed reads

__global__ __launch_bounds__(YTPB) void Yolo_59966333387037_kernel(
    const float* __restrict__ x,
    const float* __restrict__ anchors,
    float* __restrict__ out)
{
    __shared__ float sm[YC * YSTRIDE];

    const int h = blockIdx.x;      // 0..75
    const int s = blockIdx.y;      // n*A + a, 0..47
    const int a = s % YA;

    const float aw = anchors[a * 2]     * (1.0f / 608.0f);
    const float ah = anchors[a * 2 + 1] * (1.0f / 608.0f);
    const float gy = (float)h;

    const float* __restrict__ xin = x + (size_t)s * YC * YHW + (size_t)h * YW;
    const int t = threadIdx.x;

    // ---- Load + activate: 85 channels x 19 float4 (76 floats per channel row) ----
    #pragma unroll 2
    for (int i = t; i < YC * (YW / 4); i += YTPB) {
        const int c = i / (YW / 4);
        const int k = i % (YW / 4);
        const float4 v = *(const float4*)(xin + (size_t)c * YHW + 4 * k);
        float r[4] = {v.x, v.y, v.z, v.w};
        #pragma unroll
        for (int j = 0; j < 4; j++) {
            float val = r[j];
            if (c == 2) {
                val = __expf(val) * aw;
            } else if (c == 3) {
                val = __expf(val) * ah;
            } else {
                val = 1.0f / (1.0f + __expf(-val));        // sigmoid
                if (c == 0) val = (val + (float)(4 * k + j)) * (1.0f / (float)YW);
                else if (c == 1) val = (val + gy) * (1.0f / (float)YH);
            }
            sm[c * YSTRIDE + 4 * k + j] = val;
        }
    }
    __syncthreads();

    // ---- Store: tile's output is one contiguous region of 76*85 = 6460 floats ----
    float* __restrict__ o = out + ((size_t)s * YHW + (size_t)h * YW) * YC;
    #pragma unroll 2
    for (int q = t; q < (YW * YC) / 4; q += YTPB) {   // 1615 float4
        const int e = 4 * q;
        float4 v;
        float* vv = (float*)&v;
        #pragma unroll
        for (int j = 0; j < 4; j++) {
            const int ee  = e + j;
            const int c   = ee % YC;
            const int hwl = ee / YC;
            vv[j] = sm[c * YSTRIDE + hwl];
        }
        *(float4*)(o + e) = v;
    }
}

extern "C" void kernel_launch(void* const* d_in, const int* in_sizes, int n_in,
                              void* d_out, int out_size)
{
    const float* x       = (const float*)d_in[0];
    const float* anchors = (const float*)d_in[1];
    float* out           = (float*)d_out;

    dim3 grid(YH, 16 * YA);   // 76 x 48 blocks
    Yolo_59966333387037_kernel<<<grid, YTPB>>>(x, anchors, out);
}

// round 2
// speedup vs baseline: 1.0413x; 1.0413x over previous
#include <cuda_runtime.h>
#include <cuda_bf16.h>

// YOLOv3 decode: x [16, 255, 76, 76] fp32 -> out [16, 3*5776, 85] fp32
// out[n, a, hw, c] = f_c( x[n, a, c, hw] )
//   c==0: (sigmoid(v)+w)/76   c==1: (sigmoid(v)+h)/76
//   c==2: exp(v)*aw/608       c==3: exp(v)*ah/608
//   c>=4: sigmoid(v)
//
// R2: transpose on the smem-WRITE side. smem holds the tile in final output
// layout [hw][c] (6460 floats, contiguous). Store phase = pure linear
// LDS.128 -> STG.128 copy (no div/mod, no gather). R1 was issue/ALU-bound
// (issue 62%, alu 36%, DRAM 38%) on per-element %85 //85 in the store loop.

#define YW 76
#define YH 76
#define YHW 5776
#define YC 85
#define YA 3
#define YTPB 256
#define YTILE (YW * YC)          // 6460 floats per (slice, h-row) tile
#define YV4 (YTILE / 4)          // 1615 float4

__global__ __launch_bounds__(YTPB) void Yolo_59966333387037_kernel(
    const float* __restrict__ x,
    const float* __restrict__ anchors,
    float* __restrict__ out)
{
    __shared__ __align__(16) float sm[YTILE];

    const int h = blockIdx.x;      // 0..75
    const int s = blockIdx.y;      // n*A + a, 0..47
    const int a = s % YA;

    const float aw = anchors[a * 2]     * (1.0f / 608.0f);
    const float ah = anchors[a * 2 + 1] * (1.0f / 608.0f);
    const float gy = (float)h;

    const float* __restrict__ xin = x + (size_t)s * YC * YHW + (size_t)h * YW;
    const int t = threadIdx.x;

    // ---- Load + activate + transpose-into-smem ----
    // 85 channel rows x 19 float4 coalesced LDG; scattered STS.32 at stride 85.
    #pragma unroll 2
    for (int i = t; i < YC * (YW / 4); i += YTPB) {
        const int c = i / (YW / 4);        // channel 0..84
        const int k = i - c * (YW / 4);    // float4 index within row, 0..18
        const float4 v = *(const float4*)(xin + (size_t)c * YHW + 4 * k);
        float r[4] = {v.x, v.y, v.z, v.w};
        float* dst = sm + (4 * k) * YC + c;   // [hw][c] layout
        #pragma unroll
        for (int j = 0; j < 4; j++) {
            float val = r[j];
            if (c == 2) {
                val = __expf(val) * aw;
            } else if (c == 3) {
                val = __expf(val) * ah;
            } else {
                val = 1.0f / (1.0f + __expf(-val));          // sigmoid
                if (c == 0)      val = (val + (float)(4 * k + j)) * (1.0f / (float)YW);
                else if (c == 1) val = (val + gy)             * (1.0f / (float)YH);
            }
            dst[j * YC] = val;
        }
    }
    __syncthreads();

    // ---- Store: linear smem -> gmem copy, tile is one contiguous region ----
    // Tile base element offset = (s*5776 + h*76)*85 : divisible by 4 -> 16B aligned.
    float4* __restrict__ o4 = (float4*)(out + ((size_t)s * YHW + (size_t)h * YW) * YC);
    const float4* __restrict__ s4 = (const float4*)sm;
    #pragma unroll
    for (int u = 0; u < (YV4 + YTPB - 1) / YTPB; u++) {
        const int q = t + u * YTPB;
        if (q < YV4) o4[q] = s4[q];
    }
}

extern "C" void kernel_launch(void* const* d_in, const int* in_sizes, int n_in,
                              void* d_out, int out_size)
{
    const float* x       = (const float*)d_in[0];
    const float* anchors = (const float*)d_in[1];
    float* out           = (float*)d_out;

    dim3 grid(YH, 16 * YA);   // 76 x 48 blocks
    Yolo_59966333387037_kernel<<<grid, YTPB>>>(x, anchors, out);
}

// round 3
// speedup vs baseline: 1.3675x; 1.3133x over previous
#include <cuda_runtime.h>
#include <cuda_bf16.h>
#include <cstdint>

// YOLOv3 decode: x [16, 255, 76, 76] fp32 -> out [16, 3*5776, 85] fp32
// out[n, a, hw, c] = f_c( x[n, a, c, hw] ),  hw contiguous 0..5775 per channel.
//   c==0: (sig(v)+w)/76  c==1: (sig(v)+h)/76  c==2: exp(v)*aw/608
//   c==3: exp(v)*ah/608  c>=4: sig(v)
//
// R3: tile = (slice s, 64 contiguous hw). Warp-unit = (c-quad, 32 hw):
//  - 4x LDG.32, each a coalesced 128B warp read
//  - conflict-free STS.32 (lane delta = 85 words, odd)
//  - special c0..c3 path isolated to quad g==0 (warp-uniform branch)
//  - store loop replaced by one cp.async.bulk shared->global (tile is the
//    contiguous output region)

#define YHW   5776
#define YC    85
#define HWT   64
#define YTPB  256
#define NCHUNK 91          // ceil(5776/64); last chunk = 16 hw

__device__ __forceinline__ float ysig(float v) {
    return __fdividef(1.0f, 1.0f + __expf(-v));
}

__global__ __launch_bounds__(YTPB) void Yolo_59966333387037_kernel(
    const float* __restrict__ x,
    const float* __restrict__ anchors,
    float* __restrict__ out)
{
    __shared__ __align__(16) float sm[HWT * YC];   // 21760 B

    const int chunk = blockIdx.x;                  // 0..90
    const int s     = blockIdx.y;                  // n*3 + a, 0..47
    const int a     = s % 3;

    const float aw = __ldg(anchors + 2 * a)     * (1.0f / 608.0f);
    const float ah = __ldg(anchors + 2 * a + 1) * (1.0f / 608.0f);

    const int hw0 = chunk * HWT;
    const int nhw = min(HWT, YHW - hw0);           // 64 or 16 (last chunk)

    const float* __restrict__ xs = x + (size_t)s * YC * YHW + hw0;

    const int wid  = threadIdx.x >> 5;
    const int lane = threadIdx.x & 31;

    // 44 warp-units: g = 0..20 are c-quads (x2 hw-groups), g = 21 is c==84.
    #pragma unroll 3
    for (int u = wid; u < 44; u += 8) {
        const int g   = u >> 1;
        const int hwl = ((u & 1) << 5) + lane;     // 0..63 within tile
        const bool act = hwl < nhw;

        if (g < 21) {
            const int c0 = g * 4;
            if (act) {
                const float* p = xs + (size_t)c0 * YHW + hwl;
                float v0 = p[0];
                float v1 = p[YHW];
                float v2 = p[2 * YHW];
                float v3 = p[3 * YHW];
                if (g == 0) {
                    const unsigned hw = (unsigned)(hw0 + hwl);
                    const unsigned hh = (hw * 55189u) >> 22;   // hw / 76
                    const unsigned ww = hw - hh * 76u;
                    v0 = (ysig(v0) + (float)ww) * (1.0f / 76.0f);
                    v1 = (ysig(v1) + (float)hh) * (1.0f / 76.0f);
                    v2 = __expf(v2) * aw;
                    v3 = __expf(v3) * ah;
                } else {
                    v0 = ysig(v0); v1 = ysig(v1);
                    v2 = ysig(v2); v3 = ysig(v3);
                }
                float* d = sm + hwl * YC + c0;     // conflict-free STS.32 x4
                d[0] = v0; d[1] = v1; d[2] = v2; d[3] = v3;
            }
        } else {
            if (act) {
                float v = xs[(size_t)84 * YHW + hwl];
                sm[hwl * YC + 84] = ysig(v);
            }
        }
    }
    __syncthreads();

    // One bulk async store: smem tile == contiguous output region.
    if (threadIdx.x == 0) {
        asm volatile("fence.proxy.async.shared::cta;" ::: "memory");
        uint32_t saddr;
        asm("{ .reg .u64 t; cvta.to.shared.u64 t, %1; cvt.u32.u64 %0, t; }"
            : "=r"(saddr) : "l"((const void*)sm));
        float* dst = out + ((size_t)s * YHW + hw0) * YC;
        const int bytes = nhw * YC * 4;            // 21760 or 5440, 16B multiple
        asm volatile(
            "cp.async.bulk.global.shared::cta.bulk_group [%0], [%1], %2;"
            :: "l"(dst), "r"(saddr), "r"(bytes) : "memory");
        asm volatile("cp.async.bulk.commit_group;" ::: "memory");
        asm volatile("cp.async.bulk.wait_group 0;" ::: "memory");
    }
}

extern "C" void kernel_launch(void* const* d_in, const int* in_sizes, int n_in,
                              void* d_out, int out_size)
{
    const float* x       = (const float*)d_in[0];
    const float* anchors = (const float*)d_in[1];
    float* out           = (float*)d_out;

    dim3 grid(NCHUNK, 48);
    Yolo_59966333387037_kernel<<<grid, YTPB>>>(x, anchors, out);
}